// round 2
// baseline (speedup 1.0000x reference)
#include <cuda_runtime.h>
#include <math.h>
#include <stdint.h>

#define NB 16
#define NTE 64
#define NTD 32
#define NE 256
#define NH 512
#define NV 90000
#define NEGV (-1e9f)

// ---------------- device scratch (static, no allocation) ----------------
__device__ float g_qemb[NB*NTE*NE];   // [b][t][e]
__device__ float g_remb[NB*NTD*NE];   // [b][t][e]
__device__ float g_h[2][NB*NH];       // ping-pong LSTM h (enc then dec)
__device__ float g_c[2][NB*NH];       // ping-pong LSTM c
__device__ float g_attn[NB*NH];       // decoder attention state
__device__ float g_encout[NB*NTE*NH]; // [b][te][h]
__device__ float g_keys[NB*NTE*NH];   // [b][te][k]
__device__ float g_pq[NB*NH];
__device__ float g_ctx[NB*NH];
__device__ float g_A[NB*NTD*NH];      // attn2 per (b,t): row = b*NTD+t
__device__ float g_AcT[NH*NB*NTD];    // compacted + transposed A: [k][m]
__device__ int   g_outrow[NB*NTD];
__device__ int   g_nrows;

__device__ __forceinline__ float sigf(float x) { return 1.0f / (1.0f + expf(-x)); }

// ---------------- prep: embedding gather, state init, valid-row list ----------------
__global__ void prep_kernel(const int* __restrict__ enc_in, const int* __restrict__ dec_in,
                            const int* __restrict__ dlen, const float* __restrict__ emb)
{
    int idx = blockIdx.x * blockDim.x + threadIdx.x;
    int stride = gridDim.x * blockDim.x;
    for (int i = idx; i < NB*NTE*NE; i += stride) {
        int e = i & (NE - 1); int bt = i >> 8;
        g_qemb[i] = emb[(size_t)enc_in[bt] * NE + e];
    }
    for (int i = idx; i < NB*NTD*NE; i += stride) {
        int e = i & (NE - 1); int bt = i >> 8;
        g_remb[i] = emb[(size_t)dec_in[bt] * NE + e];
    }
    for (int i = idx; i < NB*NH; i += stride) {
        g_h[0][i] = 0.f; g_c[0][i] = 0.f; g_attn[i] = 0.f;
    }
    if (idx == 0) {
        int n = 0;
        for (int b = 0; b < NB; b++) {
            int L = dlen[b]; if (L > NTD) L = NTD; if (L < 0) L = 0;
            for (int t2 = 0; t2 < L; t2++) g_outrow[n++] = b * NTD + t2;
        }
        g_nrows = n;
    }
}

// ---------------- zero-fill output (invalid rows stay zero) ----------------
__global__ void zero_kernel(float4* __restrict__ out, int n4)
{
    int idx = blockIdx.x * blockDim.x + threadIdx.x;
    int stride = gridDim.x * blockDim.x;
    float4 z = make_float4(0.f, 0.f, 0.f, 0.f);
    for (int i = idx; i < n4; i += stride) out[i] = z;
}

// ---------------- encoder LSTM step (z GEMM + gates fused) ----------------
// grid 128 CTAs x 256 thr. CTA c owns j in [4c,4c+4); thread = (b, s), s = jl + 4*q.
__global__ void enc_step_kernel(const float* __restrict__ W, const float* __restrict__ bias,
                                const int* __restrict__ elen, int t)
{
    extern __shared__ float sm[];
    const int KX = NE + NH;     // 768
    const int KP = KX + 4;      // 772 (bank pad, /4 for float4)
    float* xs = sm;             // [16][KP]  x transposed-by-batch
    float* ws = sm + 16*KP;     // [16][KP]  16 gate columns
    float* zs = ws + 16*KP;     // [16][16]

    const float* h_in  = g_h[t & 1];
    const float* c_in  = g_c[t & 1];
    float* h_out = g_h[(t + 1) & 1];
    float* c_out = g_c[(t + 1) & 1];

    int tid = threadIdx.x;
    int c = blockIdx.x;

    for (int i = tid; i < 16*KX; i += 256) {
        int bb = i / KX, k = i - bb * KX;
        float v = (k < NE) ? g_qemb[(bb*NTE + t)*NE + k] : h_in[bb*NH + (k - NE)];
        xs[bb*KP + k] = v;
    }
    for (int i = tid; i < 16*KX; i += 256) {
        int k = i >> 4, gl = i & 15;
        int g = (c << 2) + (gl & 3) + ((gl >> 2) << 9);
        ws[gl*KP + k] = W[k * (4*NH) + g];
    }
    __syncthreads();

    int b = tid & 15, s = tid >> 4;
    int g = (c << 2) + (s & 3) + ((s >> 2) << 9);
    float a0 = bias[g], a1 = 0.f, a2 = 0.f, a3 = 0.f;
    const float* xp = xs + b*KP;
    const float* wp = ws + s*KP;
    #pragma unroll 8
    for (int k = 0; k < KX; k += 4) {
        float4 a = *(const float4*)(xp + k);
        float4 w = *(const float4*)(wp + k);
        a0 = fmaf(a.x, w.x, a0);
        a1 = fmaf(a.y, w.y, a1);
        a2 = fmaf(a.z, w.z, a2);
        a3 = fmaf(a.w, w.w, a3);
    }
    zs[s*16 + b] = (a0 + a1) + (a2 + a3);
    __syncthreads();

    if (s < 4) {
        int jl = s;
        int jg = (c << 2) + jl;
        float iv = zs[(jl + 0)*16 + b];
        float jv = zs[(jl + 4)*16 + b];
        float fv = zs[(jl + 8)*16 + b];
        float ov = zs[(jl + 12)*16 + b];
        float cold = c_in[b*NH + jg];
        float c2 = cold * sigf(fv + 1.f) + sigf(iv) * tanhf(jv);
        float h2 = tanhf(c2) * sigf(ov);
        bool valid = t < elen[b];
        float hold = xp[NE + jg];
        h_out[b*NH + jg] = valid ? h2 : hold;
        c_out[b*NH + jg] = valid ? c2 : cold;
        g_encout[(b*NTE + t)*NH + jg] = valid ? h2 : 0.f;
    }
}

// ---------------- decoder LSTM step (x = [emb | attn | h]) ----------------
__global__ void dec_z_kernel(const float* __restrict__ W, const float* __restrict__ bias, int t)
{
    extern __shared__ float sm[];
    const int KX = NE + 2*NH;   // 1280
    const int KP = KX + 4;      // 1284
    float* xs = sm;
    float* ws = sm + 16*KP;
    float* zs = ws + 16*KP;

    const float* h_in  = g_h[t & 1];
    const float* c_in  = g_c[t & 1];
    float* h_out = g_h[(t + 1) & 1];
    float* c_out = g_c[(t + 1) & 1];

    int tid = threadIdx.x;
    int c = blockIdx.x;

    for (int i = tid; i < 16*KX; i += 256) {
        int bb = i / KX, k = i - bb * KX;
        float v;
        if (k < NE)           v = g_remb[(bb*NTD + t)*NE + k];
        else if (k < NE + NH) v = g_attn[bb*NH + (k - NE)];
        else                  v = h_in[bb*NH + (k - NE - NH)];
        xs[bb*KP + k] = v;
    }
    for (int i = tid; i < 16*KX; i += 256) {
        int k = i >> 4, gl = i & 15;
        int g = (c << 2) + (gl & 3) + ((gl >> 2) << 9);
        ws[gl*KP + k] = W[k * (4*NH) + g];
    }
    __syncthreads();

    int b = tid & 15, s = tid >> 4;
    int g = (c << 2) + (s & 3) + ((s >> 2) << 9);
    float a0 = bias[g], a1 = 0.f, a2 = 0.f, a3 = 0.f;
    const float* xp = xs + b*KP;
    const float* wp = ws + s*KP;
    #pragma unroll 8
    for (int k = 0; k < KX; k += 4) {
        float4 a = *(const float4*)(xp + k);
        float4 w = *(const float4*)(wp + k);
        a0 = fmaf(a.x, w.x, a0);
        a1 = fmaf(a.y, w.y, a1);
        a2 = fmaf(a.z, w.z, a2);
        a3 = fmaf(a.w, w.w, a3);
    }
    zs[s*16 + b] = (a0 + a1) + (a2 + a3);
    __syncthreads();

    if (s < 4) {
        int jl = s;
        int jg = (c << 2) + jl;
        float iv = zs[(jl + 0)*16 + b];
        float jv = zs[(jl + 4)*16 + b];
        float fv = zs[(jl + 8)*16 + b];
        float ov = zs[(jl + 12)*16 + b];
        float cold = c_in[b*NH + jg];
        float c2 = cold * sigf(fv + 1.f) + sigf(iv) * tanhf(jv);
        float h2 = tanhf(c2) * sigf(ov);
        h_out[b*NH + jg] = h2;
        c_out[b*NH + jg] = c2;
    }
}

// ---------------- keys = enc_out @ W_mem : [1024,512]@[512,512] ----------------
__global__ void keys_kernel(const float* __restrict__ Wm)
{
    extern __shared__ float sm[];
    const int KX = NH, KP = NH + 4;
    float* xs = sm;            // 16 rows
    float* ws = sm + 16*KP;    // 16 n-cols
    int tid = threadIdx.x;
    int cn = blockIdx.x;       // 32 n tiles
    int cr = blockIdx.y;       // 64 row tiles

    for (int i = tid; i < 16*KX; i += 256) {
        int rl = i >> 9, k = i & 511;
        xs[rl*KP + k] = g_encout[(cr*16 + rl)*NH + k];
    }
    for (int i = tid; i < 16*KX; i += 256) {
        int k = i >> 4, nl = i & 15;
        ws[nl*KP + k] = Wm[k*NH + cn*16 + nl];
    }
    __syncthreads();

    int nl = tid & 15, rl = tid >> 4;
    float a0 = 0.f, a1 = 0.f, a2 = 0.f, a3 = 0.f;
    const float* xp = xs + rl*KP;
    const float* wp = ws + nl*KP;
    #pragma unroll 8
    for (int k = 0; k < KX; k += 4) {
        float4 a = *(const float4*)(xp + k);
        float4 w = *(const float4*)(wp + k);
        a0 = fmaf(a.x, w.x, a0);
        a1 = fmaf(a.y, w.y, a1);
        a2 = fmaf(a.z, w.z, a2);
        a3 = fmaf(a.w, w.w, a3);
    }
    g_keys[(cr*16 + rl)*NH + cn*16 + nl] = (a0 + a1) + (a2 + a3);
}

// ---------------- pq = h2 @ W_query : [16,512]@[512,512] ----------------
__global__ void pq_kernel(const float* __restrict__ Wq, int t)
{
    extern __shared__ float sm[];
    const int KX = NH, KP = NH + 4;
    float* xs = sm;
    float* ws = sm + 16*KP;
    const float* h2 = g_h[(t + 1) & 1];
    int tid = threadIdx.x;
    int c = blockIdx.x;    // 32 n tiles

    for (int i = tid; i < 16*KX; i += 256) {
        int bb = i >> 9, k = i & 511;
        xs[bb*KP + k] = h2[i];
    }
    for (int i = tid; i < 16*KX; i += 256) {
        int k = i >> 4, nl = i & 15;
        ws[nl*KP + k] = Wq[k*NH + c*16 + nl];
    }
    __syncthreads();

    int nl = tid & 15, bb = tid >> 4;
    float a0 = 0.f, a1 = 0.f, a2 = 0.f, a3 = 0.f;
    const float* xp = xs + bb*KP;
    const float* wp = ws + nl*KP;
    #pragma unroll 8
    for (int k = 0; k < KX; k += 4) {
        float4 a = *(const float4*)(xp + k);
        float4 w = *(const float4*)(wp + k);
        a0 = fmaf(a.x, w.x, a0);
        a1 = fmaf(a.y, w.y, a1);
        a2 = fmaf(a.z, w.z, a2);
        a3 = fmaf(a.w, w.w, a3);
    }
    g_pq[bb*NH + c*16 + nl] = (a0 + a1) + (a2 + a3);
}

// ---------------- attention: scores + softmax + context, one CTA per batch ----------------
__global__ void attn_kernel(const float* __restrict__ vatt, const int* __restrict__ elen, int t)
{
    __shared__ float pqs[NH];
    __shared__ float vs[NH];
    __shared__ float sc[NTE];
    int tid = threadIdx.x;
    int b = blockIdx.x;
    const float* pqp = g_pq + b*NH;

    for (int i = tid; i < NH; i += 256) { pqs[i] = pqp[i]; vs[i] = vatt[i]; }
    __syncthreads();

    int w = tid >> 5, l = tid & 31;
    int len = elen[b];
    for (int te = w; te < NTE; te += 8) {
        const float* kp = g_keys + (size_t)(b*NTE + te)*NH;
        float p = 0.f;
        for (int h = l; h < NH; h += 32)
            p += vs[h] * tanhf(kp[h] + pqs[h]);
        #pragma unroll
        for (int off = 16; off > 0; off >>= 1) p += __shfl_xor_sync(0xffffffffu, p, off);
        if (l == 0) sc[te] = (te < len) ? p : NEGV;
    }
    __syncthreads();

    if (tid < 32) {
        float a = sc[tid], b2 = sc[tid + 32];
        float m = fmaxf(a, b2);
        #pragma unroll
        for (int off = 16; off > 0; off >>= 1) m = fmaxf(m, __shfl_xor_sync(0xffffffffu, m, off));
        float e1 = expf(a - m), e2 = expf(b2 - m);
        float s = e1 + e2;
        #pragma unroll
        for (int off = 16; off > 0; off >>= 1) s += __shfl_xor_sync(0xffffffffu, s, off);
        float inv = 1.f / s;
        sc[tid] = e1 * inv; sc[tid + 32] = e2 * inv;
    }
    __syncthreads();

    for (int h = tid; h < NH; h += 256) {
        float acc = 0.f;
        const float* ep = g_encout + (size_t)b*NTE*NH + h;
        #pragma unroll 8
        for (int te = 0; te < NTE; te++)
            acc = fmaf(sc[te], ep[(size_t)te*NH], acc);
        g_ctx[b*NH + h] = acc;
    }
}

// ---------------- attn2 = [h2|ctx] @ W_attn : [16,1024]@[1024,512] ----------------
__global__ void attn2_kernel(const float* __restrict__ Wa, int t)
{
    extern __shared__ float sm[];
    const int KX = 2*NH, KP = KX + 4;   // 1024, 1028
    float* xs = sm;
    float* ws = sm + 16*KP;
    const float* h2 = g_h[(t + 1) & 1];
    int tid = threadIdx.x;
    int c = blockIdx.x;   // 32 n tiles

    for (int i = tid; i < 16*KX; i += 256) {
        int bb = i >> 10, k = i & 1023;
        float v = (k < NH) ? h2[bb*NH + k] : g_ctx[bb*NH + (k - NH)];
        xs[bb*KP + k] = v;
    }
    for (int i = tid; i < 16*KX; i += 256) {
        int k = i >> 4, nl = i & 15;
        ws[nl*KP + k] = Wa[k*NH + c*16 + nl];
    }
    __syncthreads();

    int nl = tid & 15, bb = tid >> 4;
    float a0 = 0.f, a1 = 0.f, a2 = 0.f, a3 = 0.f;
    const float* xp = xs + bb*KP;
    const float* wp = ws + nl*KP;
    #pragma unroll 8
    for (int k = 0; k < KX; k += 4) {
        float4 a = *(const float4*)(xp + k);
        float4 w = *(const float4*)(wp + k);
        a0 = fmaf(a.x, w.x, a0);
        a1 = fmaf(a.y, w.y, a1);
        a2 = fmaf(a.z, w.z, a2);
        a3 = fmaf(a.w, w.w, a3);
    }
    float acc = (a0 + a1) + (a2 + a3);
    int n = c*16 + nl;
    g_attn[bb*NH + n] = acc;                  // next-step attention state
    g_A[(bb*NTD + t)*NH + n] = acc;           // projection A row
}

// ---------------- compact valid rows + transpose A -> [k][m] ----------------
__global__ void compactT_kernel()
{
    int idx = blockIdx.x * blockDim.x + threadIdx.x;
    int stride = gridDim.x * blockDim.x;
    int nr = g_nrows;
    for (int i = idx; i < NH*NB*NTD; i += stride) {
        int k = i >> 9, m = i & 511;
        g_AcT[i] = (m < nr) ? g_A[g_outrow[m]*NH + k] : 0.f;
    }
}

// ---------------- projection: [nrows,512] @ [512,90000] ----------------
// grid (8 m-tiles fastest, 704 n-tiles). CTA tile 64x128, thread micro-tile 8x4.
__global__ void proj_kernel(const float* __restrict__ Wp, float* __restrict__ out)
{
    __shared__ float As[16*64];
    __shared__ float Bs[16*128];
    int m0 = blockIdx.x * 64;
    int n0 = blockIdx.y * 128;
    int nr = g_nrows;
    if (m0 >= nr) return;

    int tid = threadIdx.x;
    int tx = tid & 31, ty = tid >> 5;
    float acc[8][4];
    #pragma unroll
    for (int i = 0; i < 8; i++)
        #pragma unroll
        for (int j = 0; j < 4; j++) acc[i][j] = 0.f;

    for (int kt = 0; kt < NH; kt += 16) {
        for (int i = tid; i < 1024; i += 256) {
            int k = i >> 6, m = i & 63;
            As[i] = g_AcT[(kt + k)*(NB*NTD) + m0 + m];
        }
        for (int i = tid; i < 2048; i += 256) {
            int k = i >> 7, n = i & 127;
            int nn = n0 + n;
            Bs[i] = (nn < NV) ? Wp[(size_t)(kt + k)*NV + nn] : 0.f;
        }
        __syncthreads();
        #pragma unroll
        for (int k = 0; k < 16; k++) {
            float4 b4 = *(const float4*)&Bs[k*128 + tx*4];
            float4 ax = *(const float4*)&As[k*64 + ty*8];
            float4 ay = *(const float4*)&As[k*64 + ty*8 + 4];
            float av[8] = {ax.x, ax.y, ax.z, ax.w, ay.x, ay.y, ay.z, ay.w};
            #pragma unroll
            for (int i = 0; i < 8; i++) {
                acc[i][0] = fmaf(av[i], b4.x, acc[i][0]);
                acc[i][1] = fmaf(av[i], b4.y, acc[i][1]);
                acc[i][2] = fmaf(av[i], b4.z, acc[i][2]);
                acc[i][3] = fmaf(av[i], b4.w, acc[i][3]);
            }
        }
        __syncthreads();
    }

    #pragma unroll
    for (int i = 0; i < 8; i++) {
        int m = m0 + ty*8 + i;
        if (m < nr) {
            int row = g_outrow[m];
            int nn = n0 + tx*4;
            float* op = out + (size_t)row*NV + nn;
            if (nn + 3 < NV) {
                float4 v = make_float4(acc[i][0], acc[i][1], acc[i][2], acc[i][3]);
                *(float4*)op = v;
            } else {
                #pragma unroll
                for (int j = 0; j < 4; j++) if (nn + j < NV) op[j] = acc[i][j];
            }
        }
    }
}

// ---------------- launch ----------------
extern "C" void kernel_launch(void* const* d_in, const int* in_sizes, int n_in,
                              void* d_out, int out_size)
{
    const int*   enc_in  = (const int*)d_in[0];
    const int*   dec_in  = (const int*)d_in[1];
    const int*   elen    = (const int*)d_in[2];
    const int*   dlen    = (const int*)d_in[3];
    const float* emb     = (const float*)d_in[4];
    const float* W_enc   = (const float*)d_in[5];
    const float* b_enc   = (const float*)d_in[6];
    const float* W_dec   = (const float*)d_in[7];
    const float* b_dec   = (const float*)d_in[8];
    const float* W_mem   = (const float*)d_in[9];
    const float* W_query = (const float*)d_in[10];
    const float* v_att   = (const float*)d_in[11];
    const float* W_attn  = (const float*)d_in[12];
    const float* W_proj  = (const float*)d_in[13];
    float* out = (float*)d_out;

    const int smemE  = (2*16*(NE + NH + 4) + 256) * 4;     //  99840 B
    const int smemD  = (2*16*(NE + 2*NH + 4) + 256) * 4;   // 165376 B
    const int smemS  = (2*16*(NH + 4)) * 4;                //  66048 B
    const int smemA2 = (2*16*(2*NH + 4)) * 4;              // 131584 B

    cudaFuncSetAttribute(enc_step_kernel, cudaFuncAttributeMaxDynamicSharedMemorySize, smemE);
    cudaFuncSetAttribute(dec_z_kernel,    cudaFuncAttributeMaxDynamicSharedMemorySize, smemD);
    cudaFuncSetAttribute(pq_kernel,       cudaFuncAttributeMaxDynamicSharedMemorySize, smemS);
    cudaFuncSetAttribute(keys_kernel,     cudaFuncAttributeMaxDynamicSharedMemorySize, smemS);
    cudaFuncSetAttribute(attn2_kernel,    cudaFuncAttributeMaxDynamicSharedMemorySize, smemA2);

    prep_kernel<<<256, 256>>>(enc_in, dec_in, dlen, emb);
    zero_kernel<<<1024, 256>>>((float4*)out, NB*NTD*NV/4);

    for (int t = 0; t < NTE; t++)
        enc_step_kernel<<<128, 256, smemE>>>(W_enc, b_enc, elen, t);

    keys_kernel<<<dim3(32, 64), 256, smemS>>>(W_mem);

    for (int t = 0; t < NTD; t++) {
        dec_z_kernel<<<128, 256, smemD>>>(W_dec, b_dec, t);
        pq_kernel<<<32, 256, smemS>>>(W_query, t);
        attn_kernel<<<16, 256>>>(v_att, elen, t);
        attn2_kernel<<<32, 256, smemA2>>>(W_attn, t);
    }

    compactT_kernel<<<256, 256>>>();
    proj_kernel<<<dim3(8, 704), 256>>>(W_proj, out);
}

// round 3
// speedup vs baseline: 1.0876x; 1.0876x over previous
#include <cuda_runtime.h>
#include <math.h>
#include <stdint.h>

#define NB 16
#define NTE 64
#define NTD 32
#define NE 256
#define NH 512
#define NG 2048
#define NV 90000
#define NEGV (-1e9f)

typedef unsigned long long u64;

// ---------------- device scratch (static, no allocation) ----------------
__device__ float g_qemb[NB*NTE*NE];   // [b][t][e]
__device__ float g_remb[NB*NTD*NE];   // [b][t][e]
__device__ float g_h[2][NB*NH];       // ping-pong LSTM h
__device__ float g_c[2][NB*NH];       // ping-pong LSTM c
__device__ float g_attn[NB*NH];       // decoder attention state
__device__ float g_encout[NB*NTE*NH]; // [b][te][h]
__device__ float g_keys[NB*NTE*NH];   // [b][te][k]
__device__ float g_A[NB*NTD*NH];      // attn2 rows: row = b*NTD+t
__device__ float g_AcT[NH*NB*NTD];    // compacted+transposed A: [k][m]
__device__ int   g_outrow[NB*NTD];
__device__ int   g_nrows;
__device__ float g_W2e[768*NG];       // permuted W_enc: [k][jblk][jl*4+q]
__device__ float g_W2d[1280*NG];      // permuted W_dec

__device__ __forceinline__ float sigf(float x) { return 1.0f / (1.0f + expf(-x)); }

__device__ __forceinline__ u64 packdup(float v) {
    u64 r;
    asm("mov.b64 %0, {%1, %1};" : "=l"(r) : "r"(__float_as_uint(v)));
    return r;
}
__device__ __forceinline__ void fma2(u64& d, u64 a, u64 b) {
    asm("fma.rn.f32x2 %0, %1, %2, %0;" : "+l"(d) : "l"(a), "l"(b));
}
__device__ __forceinline__ void unpack2(u64 v, float& lo, float& hi) {
    unsigned l, h;
    asm("mov.b64 {%0, %1}, %2;" : "=r"(l), "=r"(h) : "l"(v));
    lo = __uint_as_float(l); hi = __uint_as_float(h);
}

// ---------------- prep: embedding gather, state init, valid-row list ----------------
__global__ void prep_kernel(const int* __restrict__ enc_in, const int* __restrict__ dec_in,
                            const int* __restrict__ dlen, const float* __restrict__ emb)
{
    int idx = blockIdx.x * blockDim.x + threadIdx.x;
    int stride = gridDim.x * blockDim.x;
    for (int i = idx; i < NB*NTE*NE; i += stride) {
        int e = i & (NE - 1); int bt = i >> 8;
        g_qemb[i] = emb[(size_t)enc_in[bt] * NE + e];
    }
    for (int i = idx; i < NB*NTD*NE; i += stride) {
        int e = i & (NE - 1); int bt = i >> 8;
        g_remb[i] = emb[(size_t)dec_in[bt] * NE + e];
    }
    for (int i = idx; i < NB*NH; i += stride) {
        g_h[0][i] = 0.f; g_c[0][i] = 0.f; g_attn[i] = 0.f;
    }
    if (idx == 0) {
        int n = 0;
        for (int b = 0; b < NB; b++) {
            int L = dlen[b]; if (L > NTD) L = NTD; if (L < 0) L = 0;
            for (int t2 = 0; t2 < L; t2++) g_outrow[n++] = b * NTD + t2;
        }
        g_nrows = n;
    }
}

// ---------------- permute LSTM weights into gate-blocked layout ----------------
// W2[k][blk*16 + jl*4 + q] = W[k][q*512 + blk*4 + jl]
__global__ void permW_kernel(const float* __restrict__ We, const float* __restrict__ Wd)
{
    int idx = blockIdx.x * blockDim.x + threadIdx.x;
    int stride = gridDim.x * blockDim.x;
    for (int i = idx; i < 768*NG; i += stride) {
        int k = i >> 11, g2 = i & (NG - 1);
        int blk = g2 >> 4, x = g2 & 15, jl = x >> 2, q = x & 3;
        g_W2e[i] = We[(size_t)k*NG + q*NH + (blk << 2) + jl];
    }
    for (int i = idx; i < 1280*NG; i += stride) {
        int k = i >> 11, g2 = i & (NG - 1);
        int blk = g2 >> 4, x = g2 & 15, jl = x >> 2, q = x & 3;
        g_W2d[i] = Wd[(size_t)k*NG + q*NH + (blk << 2) + jl];
    }
}

// ---------------- zero-fill output ----------------
__global__ void zero_kernel(float4* __restrict__ out, int n4)
{
    int idx = blockIdx.x * blockDim.x + threadIdx.x;
    int stride = gridDim.x * blockDim.x;
    float4 z = make_float4(0.f, 0.f, 0.f, 0.f);
    for (int i = idx; i < n4; i += stride) out[i] = z;
}

// ---------------- encoder LSTM step (coalesced, f32x2, fused pointwise) ----------------
// grid 128 CTAs x 256 thr. CTA c owns j in [4c,4c+4) (x4 quadrants = 16 gates).
// thread = (gl 0..15 gate, s 0..15 k-split of 48).
__global__ void enc_step2(const float* __restrict__ bias, const int* __restrict__ elen, int t)
{
    extern __shared__ float sm[];
    float* xs = sm;               // [768][16]  x transposed to [k][b]
    float* zp = sm + 768*16;      // [16 s][16 gl][16 b]
    float* zz = zp + 4096;        // [16 gl][16 b]

    const float* h_in  = g_h[t & 1];
    const float* c_in  = g_c[t & 1];
    float* h_out = g_h[(t + 1) & 1];
    float* c_out = g_c[(t + 1) & 1];

    int tid = threadIdx.x;
    int c = blockIdx.x;

    for (int i = tid; i < 16*768; i += 256) {
        int b = i / 768, k = i - b*768;
        float v = (k < NE) ? g_qemb[(b*NTE + t)*NE + k] : h_in[b*NH + (k - NE)];
        xs[k*16 + b] = v;
    }
    __syncthreads();

    int gl = tid & 15, s = tid >> 4;
    const float* Wp = g_W2e + (c << 4) + gl;
    u64 acc[8];
    #pragma unroll
    for (int p = 0; p < 8; p++) acc[p] = 0ULL;

    int k0 = s * 48;
    #pragma unroll 4
    for (int k = k0; k < k0 + 48; k++) {
        u64 wp2 = packdup(__ldg(Wp + (size_t)k*NG));
        const u64* xk = (const u64*)(xs + k*16);
        #pragma unroll
        for (int p = 0; p < 8; p++) fma2(acc[p], xk[p], wp2);
    }

    #pragma unroll
    for (int p = 0; p < 8; p++) {
        float lo, hi; unpack2(acc[p], lo, hi);
        zp[tid*16 + 2*p]   = lo;
        zp[tid*16 + 2*p+1] = hi;
    }
    __syncthreads();

    {   // reduce over 16 splits, add bias
        int g2 = tid >> 4, b = tid & 15;
        float sum = 0.f;
        #pragma unroll
        for (int ss = 0; ss < 16; ss++) sum += zp[(ss*16 + g2)*16 + b];
        zz[g2*16 + b] = sum + bias[(g2 & 3)*NH + (c << 2) + (g2 >> 2)];
    }
    __syncthreads();

    if (tid < 64) {
        int jl = tid >> 4, b = tid & 15;
        int jg = (c << 2) + jl;
        float iv = zz[(jl*4 + 0)*16 + b];
        float jv = zz[(jl*4 + 1)*16 + b];
        float fv = zz[(jl*4 + 2)*16 + b];
        float ov = zz[(jl*4 + 3)*16 + b];
        float cold = c_in[b*NH + jg];
        float c2 = cold * sigf(fv + 1.f) + sigf(iv) * tanhf(jv);
        float h2 = tanhf(c2) * sigf(ov);
        bool valid = t < elen[b];
        float hold = xs[(NE + jg)*16 + b];
        h_out[b*NH + jg] = valid ? h2 : hold;
        c_out[b*NH + jg] = valid ? c2 : cold;
        g_encout[((size_t)b*NTE + t)*NH + jg] = valid ? h2 : 0.f;
    }
}

// ---------------- decoder LSTM step (x = [emb | attn | h], K=1280) ----------------
__global__ void dec_step2(const float* __restrict__ bias, int t)
{
    extern __shared__ float sm[];
    float* xs = sm;               // [1280][16]
    float* zp = sm + 1280*16;     // [16][16][16]
    float* zz = zp + 4096;

    const float* h_in  = g_h[t & 1];
    const float* c_in  = g_c[t & 1];
    float* h_out = g_h[(t + 1) & 1];
    float* c_out = g_c[(t + 1) & 1];

    int tid = threadIdx.x;
    int c = blockIdx.x;

    for (int i = tid; i < 16*1280; i += 256) {
        int b = i / 1280, k = i - b*1280;
        float v;
        if (k < NE)           v = g_remb[(b*NTD + t)*NE + k];
        else if (k < NE + NH) v = g_attn[b*NH + (k - NE)];
        else                  v = h_in[b*NH + (k - NE - NH)];
        xs[k*16 + b] = v;
    }
    __syncthreads();

    int gl = tid & 15, s = tid >> 4;
    const float* Wp = g_W2d + (c << 4) + gl;
    u64 acc[8];
    #pragma unroll
    for (int p = 0; p < 8; p++) acc[p] = 0ULL;

    int k0 = s * 80;
    #pragma unroll 4
    for (int k = k0; k < k0 + 80; k++) {
        u64 wp2 = packdup(__ldg(Wp + (size_t)k*NG));
        const u64* xk = (const u64*)(xs + k*16);
        #pragma unroll
        for (int p = 0; p < 8; p++) fma2(acc[p], xk[p], wp2);
    }

    #pragma unroll
    for (int p = 0; p < 8; p++) {
        float lo, hi; unpack2(acc[p], lo, hi);
        zp[tid*16 + 2*p]   = lo;
        zp[tid*16 + 2*p+1] = hi;
    }
    __syncthreads();

    {
        int g2 = tid >> 4, b = tid & 15;
        float sum = 0.f;
        #pragma unroll
        for (int ss = 0; ss < 16; ss++) sum += zp[(ss*16 + g2)*16 + b];
        zz[g2*16 + b] = sum + bias[(g2 & 3)*NH + (c << 2) + (g2 >> 2)];
    }
    __syncthreads();

    if (tid < 64) {
        int jl = tid >> 4, b = tid & 15;
        int jg = (c << 2) + jl;
        float iv = zz[(jl*4 + 0)*16 + b];
        float jv = zz[(jl*4 + 1)*16 + b];
        float fv = zz[(jl*4 + 2)*16 + b];
        float ov = zz[(jl*4 + 3)*16 + b];
        float cold = c_in[b*NH + jg];
        float c2 = cold * sigf(fv + 1.f) + sigf(iv) * tanhf(jv);
        float h2 = tanhf(c2) * sigf(ov);
        h_out[b*NH + jg] = h2;
        c_out[b*NH + jg] = c2;
    }
}

// ---------------- keys = enc_out @ W_mem : [1024,512]@[512,512] ----------------
__global__ void keys_kernel(const float* __restrict__ Wm)
{
    extern __shared__ float sm[];
    const int KX = NH, KP = NH + 4;
    float* xs = sm;
    float* ws = sm + 16*KP;
    int tid = threadIdx.x;
    int cn = blockIdx.x;
    int cr = blockIdx.y;

    for (int i = tid; i < 16*KX; i += 256) {
        int rl = i >> 9, k = i & 511;
        xs[rl*KP + k] = g_encout[(cr*16 + rl)*NH + k];
    }
    for (int i = tid; i < 16*KX; i += 256) {
        int k = i >> 4, nl = i & 15;
        ws[nl*KP + k] = Wm[k*NH + cn*16 + nl];
    }
    __syncthreads();

    int nl = tid & 15, rl = tid >> 4;
    float a0 = 0.f, a1 = 0.f, a2 = 0.f, a3 = 0.f;
    const float* xp = xs + rl*KP;
    const float* wp = ws + nl*KP;
    #pragma unroll 8
    for (int k = 0; k < KX; k += 4) {
        float4 a = *(const float4*)(xp + k);
        float4 w = *(const float4*)(wp + k);
        a0 = fmaf(a.x, w.x, a0);
        a1 = fmaf(a.y, w.y, a1);
        a2 = fmaf(a.z, w.z, a2);
        a3 = fmaf(a.w, w.w, a3);
    }
    g_keys[(cr*16 + rl)*NH + cn*16 + nl] = (a0 + a1) + (a2 + a3);
}

// ---------------- fused decoder tail: pq -> scores -> softmax -> ctx -> attn2 ----------------
// grid 16 (one CTA per batch), 512 threads.
__global__ void dec_att_kernel(const float* __restrict__ Wq, const float* __restrict__ vatt,
                               const float* __restrict__ Wa, const int* __restrict__ elen, int t)
{
    __shared__ float cat[2*NH];    // [h2 | ctx]
    __shared__ float pqs[NH];
    __shared__ float vs[NH];
    __shared__ float part[2*NH];   // split-k partials
    __shared__ float sc[NTE];

    int tid = threadIdx.x;
    int b = blockIdx.x;
    const float* h2p = g_h[(t + 1) & 1] + b*NH;

    cat[tid] = h2p[tid & (NH-1)];          // tid<512 loads h2
    vs[tid & (NH-1)] = vatt[tid & (NH-1)];
    __syncthreads();

    // ---- pq = h2 @ Wq, 256 n-pairs x 2 k-splits ----
    {
        int np = tid & 255, ks = tid >> 8;
        int k0 = ks * 256;
        u64 acc = 0ULL;
        #pragma unroll 8
        for (int k = k0; k < k0 + 256; k++) {
            u64 xp2 = packdup(cat[k]);
            u64 w = *(const u64*)&Wq[(size_t)k*NH + np*2];
            fma2(acc, xp2, w);
        }
        float lo, hi; unpack2(acc, lo, hi);
        part[ks*NH + np*2] = lo;
        part[ks*NH + np*2 + 1] = hi;
    }
    __syncthreads();
    pqs[tid & (NH-1)] = part[tid & (NH-1)] + part[NH + (tid & (NH-1))];
    __syncthreads();

    // ---- scores ----
    int w = tid >> 5, l = tid & 31;
    int len = elen[b];
    for (int te = w; te < NTE; te += 16) {
        const float* kp = g_keys + ((size_t)b*NTE + te)*NH;
        float p = 0.f;
        for (int h = l; h < NH; h += 32)
            p += vs[h] * tanhf(kp[h] + pqs[h]);
        #pragma unroll
        for (int off = 16; off > 0; off >>= 1) p += __shfl_xor_sync(0xffffffffu, p, off);
        if (l == 0) sc[te] = (te < len) ? p : NEGV;
    }
    __syncthreads();

    // ---- softmax over 64 ----
    if (tid < 32) {
        float a = sc[tid], b2 = sc[tid + 32];
        float m = fmaxf(a, b2);
        #pragma unroll
        for (int off = 16; off > 0; off >>= 1) m = fmaxf(m, __shfl_xor_sync(0xffffffffu, m, off));
        float e1 = expf(a - m), e2 = expf(b2 - m);
        float s = e1 + e2;
        #pragma unroll
        for (int off = 16; off > 0; off >>= 1) s += __shfl_xor_sync(0xffffffffu, s, off);
        float inv = 1.f / s;
        sc[tid] = e1 * inv; sc[tid + 32] = e2 * inv;
    }
    __syncthreads();

    // ---- ctx ----
    {
        float acc = 0.f;
        const float* ep = g_encout + (size_t)b*NTE*NH + tid;
        #pragma unroll 8
        for (int te = 0; te < NTE; te++)
            acc = fmaf(sc[te], ep[(size_t)te*NH], acc);
        cat[NH + tid] = acc;
    }
    __syncthreads();

    // ---- attn2 = cat @ Wa, 256 n-pairs x 2 k-splits of 512 ----
    {
        int np = tid & 255, ks = tid >> 8;
        int k0 = ks * NH;
        u64 acc = 0ULL;
        #pragma unroll 8
        for (int k = k0; k < k0 + NH; k++) {
            u64 xp2 = packdup(cat[k]);
            u64 wv = *(const u64*)&Wa[(size_t)k*NH + np*2];
            fma2(acc, xp2, wv);
        }
        float lo, hi; unpack2(acc, lo, hi);
        part[ks*NH + np*2] = lo;
        part[ks*NH + np*2 + 1] = hi;
    }
    __syncthreads();
    {
        int n = tid & (NH-1);
        float v = part[n] + part[NH + n];
        g_attn[b*NH + n] = v;
        g_A[((size_t)b*NTD + t)*NH + n] = v;
    }
}

// ---------------- compact valid rows + transpose A -> [k][m] ----------------
__global__ void compactT_kernel()
{
    int idx = blockIdx.x * blockDim.x + threadIdx.x;
    int stride = gridDim.x * blockDim.x;
    int nr = g_nrows;
    for (int i = idx; i < NH*NB*NTD; i += stride) {
        int k = i >> 9, m = i & 511;
        g_AcT[i] = (m < nr) ? g_A[g_outrow[m]*NH + k] : 0.f;
    }
}

// ---------------- projection: [nrows,512] @ [512,90000], f32x2 ----------------
__global__ void proj_kernel(const float* __restrict__ Wp, float* __restrict__ out)
{
    __shared__ float2 As2[16*64];  // duplicated A values -> LDS.64 gives (a,a)
    __shared__ float  Bs[16*128];
    int m0 = blockIdx.x * 64;
    int n0 = blockIdx.y * 128;
    int nr = g_nrows;
    if (m0 >= nr) return;

    int tid = threadIdx.x;
    int tx = tid & 31, ty = tid >> 5;
    u64 acc2[8][2];
    #pragma unroll
    for (int i = 0; i < 8; i++) { acc2[i][0] = 0ULL; acc2[i][1] = 0ULL; }

    for (int kt = 0; kt < NH; kt += 16) {
        for (int i = tid; i < 1024; i += 256) {
            int k = i >> 6, m = i & 63;
            float v = g_AcT[(kt + k)*(NB*NTD) + m0 + m];
            As2[i] = make_float2(v, v);
        }
        for (int i = tid; i < 2048; i += 256) {
            int k = i >> 7, n = i & 127;
            int nn = n0 + n;
            Bs[i] = (nn < NV) ? Wp[(size_t)(kt + k)*NV + nn] : 0.f;
        }
        __syncthreads();
        #pragma unroll
        for (int k = 0; k < 16; k++) {
            u64 b01 = *(const u64*)&Bs[k*128 + tx*4];
            u64 b23 = *(const u64*)&Bs[k*128 + tx*4 + 2];
            const u64* ap = (const u64*)&As2[k*64 + ty*8];
            #pragma unroll
            for (int i = 0; i < 8; i++) {
                u64 a = ap[i];
                fma2(acc2[i][0], a, b01);
                fma2(acc2[i][1], a, b23);
            }
        }
        __syncthreads();
    }

    #pragma unroll
    for (int i = 0; i < 8; i++) {
        int m = m0 + ty*8 + i;
        if (m < nr) {
            int row = g_outrow[m];
            int nn = n0 + tx*4;
            float v0, v1, v2, v3;
            unpack2(acc2[i][0], v0, v1);
            unpack2(acc2[i][1], v2, v3);
            float* op = out + (size_t)row*NV + nn;
            if (nn + 3 < NV) {
                *(float4*)op = make_float4(v0, v1, v2, v3);
            } else {
                float vv[4] = {v0, v1, v2, v3};
                #pragma unroll
                for (int j = 0; j < 4; j++) if (nn + j < NV) op[j] = vv[j];
            }
        }
    }
}

// ---------------- launch ----------------
extern "C" void kernel_launch(void* const* d_in, const int* in_sizes, int n_in,
                              void* d_out, int out_size)
{
    const int*   enc_in  = (const int*)d_in[0];
    const int*   dec_in  = (const int*)d_in[1];
    const int*   elen    = (const int*)d_in[2];
    const int*   dlen    = (const int*)d_in[3];
    const float* emb     = (const float*)d_in[4];
    const float* W_enc   = (const float*)d_in[5];
    const float* b_enc   = (const float*)d_in[6];
    const float* W_dec   = (const float*)d_in[7];
    const float* b_dec   = (const float*)d_in[8];
    const float* W_mem   = (const float*)d_in[9];
    const float* W_query = (const float*)d_in[10];
    const float* v_att   = (const float*)d_in[11];
    const float* W_attn  = (const float*)d_in[12];
    const float* W_proj  = (const float*)d_in[13];
    float* out = (float*)d_out;

    const int smemE = (768*16 + 4096 + 256) * 4;    //  66560 B
    const int smemD = (1280*16 + 4096 + 256) * 4;   //  99328 B
    const int smemK = (2*16*(NH + 4)) * 4;          //  66048 B

    cudaFuncSetAttribute(enc_step2,   cudaFuncAttributeMaxDynamicSharedMemorySize, smemE);
    cudaFuncSetAttribute(dec_step2,   cudaFuncAttributeMaxDynamicSharedMemorySize, smemD);
    cudaFuncSetAttribute(keys_kernel, cudaFuncAttributeMaxDynamicSharedMemorySize, smemK);

    prep_kernel<<<256, 256>>>(enc_in, dec_in, dlen, emb);
    permW_kernel<<<512, 256>>>(W_enc, W_dec);
    zero_kernel<<<1024, 256>>>((float4*)out, NB*NTD*NV/4);

    for (int t = 0; t < NTE; t++)
        enc_step2<<<128, 256, smemE>>>(b_enc, elen, t);

    keys_kernel<<<dim3(32, 64), 256, smemK>>>(W_mem);

    for (int t = 0; t < NTD; t++) {
        dec_step2<<<128, 256, smemD>>>(b_dec, t);
        dec_att_kernel<<<16, 512>>>(W_query, v_att, W_attn, elen, t);
    }

    compactT_kernel<<<256, 256>>>();
    proj_kernel<<<dim3(8, 704), 256>>>(W_proj, out);
}